// round 11
// baseline (speedup 1.0000x reference)
#include <cuda_runtime.h>

#define BATCH 8
#define N_SEQ 1024
#define CDIM  256
#define RREL  16

// Padded smem strides (R9: 2-way STS conflicts instead of 4-way)
#define SA 132
#define SB 68

// Scratch (device globals — no allocation allowed)
__device__ __align__(16) float g_Gt[CDIM * CDIM];        // Gt[m][k] = sum_c Wq[c][k]*Wk[c][m]
__device__ __align__(16) float g_wu[CDIM];               // Wq^T @ b_k
__device__ __align__(16) float g_wv[CDIM];               // Wk^T @ b_q
__device__ float g_cst;                                  // b_q . b_k
__device__ __align__(16) float g_A[BATCH * N_SEQ * CDIM];// Q @ G  (8 MB)
__device__ __align__(16) float g_u[BATCH * N_SEQ];
__device__ __align__(16) float g_v[BATCH * N_SEQ];
__device__ __align__(16) float g_Rt[RREL * N_SEQ * N_SEQ]; // R_map transposed [r][i][j] (64 MB)

// ---------------------------------------------------------------------------
// prep_w: blocks 0..255 compute Gt; block 256 computes wu/wv/cst.
// R11: wu/wv loop uses 8 independent accumulator pairs (unrolled) so the
// 256 c-iterations pipeline on load latency (MLP ~16) instead of serializing.
// ---------------------------------------------------------------------------
__global__ void prep_w(const float* __restrict__ Wq, const float* __restrict__ Wk,
                       const float* __restrict__ bq, const float* __restrict__ bk) {
    int tid = threadIdx.x;

    if (blockIdx.x == 256) {
        float su[8] = {}, sv[8] = {};
#pragma unroll
        for (int c0 = 0; c0 < CDIM; c0 += 8) {
#pragma unroll
            for (int q = 0; q < 8; q++) {
                int c = c0 + q;
                su[q] += Wq[c * CDIM + tid] * bk[c];
                sv[q] += Wk[c * CDIM + tid] * bq[c];
            }
        }
        float fu = ((su[0] + su[1]) + (su[2] + su[3])) + ((su[4] + su[5]) + (su[6] + su[7]));
        float fv = ((sv[0] + sv[1]) + (sv[2] + sv[3])) + ((sv[4] + sv[5]) + (sv[6] + sv[7]));
        g_wu[tid] = fu;
        g_wv[tid] = fv;
        __shared__ float red[256];
        red[tid] = bq[tid] * bk[tid];
        __syncthreads();
        for (int s = 128; s > 0; s >>= 1) {
            if (tid < s) red[tid] += red[tid + s];
            __syncthreads();
        }
        if (tid == 0) g_cst = red[0];
        return;
    }

    int bx = blockIdx.x;
    int mt = bx >> 4;
    int kt = bx & 15;
    int tm = tid >> 4;
    int tk = tid & 15;
    int lc = tid >> 4;
    int li = tid & 15;

    __shared__ float sq[16][16];
    __shared__ float sk[16][16];

    float acc = 0.f;
    for (int c0 = 0; c0 < CDIM; c0 += 16) {
        sq[lc][li] = Wq[(c0 + lc) * CDIM + kt * 16 + li];
        sk[lc][li] = Wk[(c0 + lc) * CDIM + mt * 16 + li];
        __syncthreads();
#pragma unroll
        for (int cc = 0; cc < 16; cc++)
            acc += sq[cc][tk] * sk[cc][tm];
        __syncthreads();
    }
    g_Gt[(mt * 16 + tm) * CDIM + kt * 16 + tk] = acc;
}

// ---------------------------------------------------------------------------
// mega: heterogeneous launch that fills the machine.
//   blocks [0,256):         gemm_A  (A = Q @ G), 128x64 tile, 8x4 micro
//   blocks [256,4352):      Rt transpose (R_map[i][j][r] -> g_Rt[r][i][j])
//   blocks [4352,5376):     compute_uv
// ---------------------------------------------------------------------------
__global__ __launch_bounds__(256, 2) void mega(const float* __restrict__ Q,
                                               const float* __restrict__ K,
                                               const float* __restrict__ Rmap) {
    __shared__ __align__(16) float smem[6400];   // union buffer (25.6 KB)
    int tid = threadIdx.x;
    int bx = blockIdx.x;

    if (bx < 256) {
        // ================= gemm_A branch =================
        int mt = bx & 3;
        int rt = bx >> 2;
        int tx = tid & 15;
        int ty = tid >> 4;
        int lrow = tid >> 2;
        int lk = (tid & 3) << 2;

        float (*As)[16][SA] = (float (*)[16][SA])smem;
        float (*Bs)[16][SB] = (float (*)[16][SB])(smem + 2 * 16 * SA);

        const float* Ap = Q + (size_t)rt * 128 * CDIM;
        const float* Bp = g_Gt + (size_t)mt * 64 * CDIM;

        float4 ra0, ra1, rb0;

        auto ldg_stage = [&](int k0) {
            ra0 = *(const float4*)(Ap + (size_t)lrow * CDIM + k0 + lk);
            ra1 = *(const float4*)(Ap + (size_t)(64 + lrow) * CDIM + k0 + lk);
            rb0 = *(const float4*)(Bp + (size_t)lrow * CDIM + k0 + lk);
        };
        auto sts_stage = [&](int buf) {
            As[buf][lk + 0][lrow] = ra0.x; As[buf][lk + 1][lrow] = ra0.y;
            As[buf][lk + 2][lrow] = ra0.z; As[buf][lk + 3][lrow] = ra0.w;
            As[buf][lk + 0][64 + lrow] = ra1.x; As[buf][lk + 1][64 + lrow] = ra1.y;
            As[buf][lk + 2][64 + lrow] = ra1.z; As[buf][lk + 3][64 + lrow] = ra1.w;
            Bs[buf][lk + 0][lrow] = rb0.x; Bs[buf][lk + 1][lrow] = rb0.y;
            Bs[buf][lk + 2][lrow] = rb0.z; Bs[buf][lk + 3][lrow] = rb0.w;
        };

        float acc[8][4] = {};

        ldg_stage(0);
        sts_stage(0);
        __syncthreads();

        for (int s = 0; s < 16; s++) {
            int cur = s & 1;
            if (s < 15) ldg_stage((s + 1) * 16);
#pragma unroll
            for (int kk = 0; kk < 16; kk++) {
                float4 a0 = *(const float4*)&As[cur][kk][ty * 8];
                float4 a1 = *(const float4*)&As[cur][kk][ty * 8 + 4];
                float4 b0 = *(const float4*)&Bs[cur][kk][tx * 4];
                float av[8] = {a0.x, a0.y, a0.z, a0.w, a1.x, a1.y, a1.z, a1.w};
                float bv[4] = {b0.x, b0.y, b0.z, b0.w};
#pragma unroll
                for (int ii = 0; ii < 8; ii++)
#pragma unroll
                    for (int jj = 0; jj < 4; jj++)
                        acc[ii][jj] += av[ii] * bv[jj];
            }
            if (s < 15) {
                sts_stage(cur ^ 1);
                __syncthreads();
            }
        }

        int row = rt * 128 + ty * 8;
        int m = mt * 64 + tx * 4;
#pragma unroll
        for (int ii = 0; ii < 8; ii++) {
            float4 o = {acc[ii][0], acc[ii][1], acc[ii][2], acc[ii][3]};
            *(float4*)&g_A[(size_t)(row + ii) * CDIM + m] = o;
        }
        return;
    }

    if (bx < 256 + 4096) {
        // ================= Rt transpose branch =================
        int tb = bx - 256;                  // 0..4095
        int i  = tb >> 2;                   // 0..1023
        int j0 = (tb & 3) << 8;             // 0,256,512,768
        float* s = smem;                    // uses 256*17 = 4352 floats
        const float4* src = (const float4*)(Rmap + ((size_t)i * N_SEQ + j0) * RREL);
#pragma unroll
        for (int q = 0; q < 4; q++) {
            int idx = q * 256 + tid;        // 0..1023 float4s
            float4 f = src[idx];
            int j = idx >> 2;
            int rq = (idx & 3) << 2;
            s[j * 17 + rq + 0] = f.x; s[j * 17 + rq + 1] = f.y;
            s[j * 17 + rq + 2] = f.z; s[j * 17 + rq + 3] = f.w;
        }
        __syncthreads();
        int jq = (tid & 63) << 2;
        int r0 = tid >> 6;                  // 0..3
#pragma unroll
        for (int w = 0; w < 4; w++) {
            int r = r0 * 4 + w;
            float4 o;
            o.x = s[(jq + 0) * 17 + r];
            o.y = s[(jq + 1) * 17 + r];
            o.z = s[(jq + 2) * 17 + r];
            o.w = s[(jq + 3) * 17 + r];
            *(float4*)&g_Rt[((size_t)r * N_SEQ + i) * N_SEQ + j0 + jq] = o;
        }
        return;
    }

    // ================= compute_uv branch =================
    {
        int ub = bx - (256 + 4096);         // 0..1023
        int warp = tid >> 5;
        int lane = tid & 31;
        int row = ub * 8 + warp;
        const float* qr = Q + (size_t)row * CDIM;
        const float* kr = K + (size_t)row * CDIM;
        float au = 0.f, av = 0.f;
#pragma unroll
        for (int t = 0; t < 8; t++) {
            int c = lane + t * 32;
            au += qr[c] * g_wu[c];
            av += kr[c] * g_wv[c];
        }
#pragma unroll
        for (int o = 16; o > 0; o >>= 1) {
            au += __shfl_down_sync(0xffffffffu, au, o);
            av += __shfl_down_sync(0xffffffffu, av, o);
        }
        if (lane == 0) {
            g_u[row] = au;
            g_v[row] = av;
        }
    }
}

// ---------------------------------------------------------------------------
// main_fused (identical to R9/R10 best): 128(i) x 64(j) tile, 8x4 micro,
// 256 threads, occ-3, padded smem, Rt epilogue, streaming stores.
// ---------------------------------------------------------------------------
__global__ __launch_bounds__(256, 3) void main_fused(const float* __restrict__ Key,
                                                     float* __restrict__ out) {
    int b = blockIdx.x;
    int tile = blockIdx.y;        // 0..127
    int it = tile >> 4;           // 0..7   (128 i-rows each)
    int jt = tile & 15;           // 0..15  (64 j-cols each)
    int tid = threadIdx.x;
    int tx = tid & 15;            // j dir (4 each)
    int ty = tid >> 4;            // i dir (8 each)
    int lrow = tid >> 2;          // 0..63
    int lk = (tid & 3) << 2;      // 0,4,8,12

    __shared__ __align__(16) float As[2][16][SA];  // [buf][k][i] padded
    __shared__ __align__(16) float Bs[2][16][SB];  // [buf][k][j] padded

    const float* Ap = g_A + ((size_t)b * N_SEQ + it * 128) * CDIM;
    const float* Bp = Key + ((size_t)b * N_SEQ + jt * 64) * CDIM;

    float4 ra0, ra1, rb0;

    auto ldg_stage = [&](int k0) {
        ra0 = *(const float4*)(Ap + (size_t)lrow * CDIM + k0 + lk);
        ra1 = *(const float4*)(Ap + (size_t)(64 + lrow) * CDIM + k0 + lk);
        rb0 = *(const float4*)(Bp + (size_t)lrow * CDIM + k0 + lk);
    };
    auto sts_stage = [&](int buf) {
        As[buf][lk + 0][lrow] = ra0.x; As[buf][lk + 1][lrow] = ra0.y;
        As[buf][lk + 2][lrow] = ra0.z; As[buf][lk + 3][lrow] = ra0.w;
        As[buf][lk + 0][64 + lrow] = ra1.x; As[buf][lk + 1][64 + lrow] = ra1.y;
        As[buf][lk + 2][64 + lrow] = ra1.z; As[buf][lk + 3][64 + lrow] = ra1.w;
        Bs[buf][lk + 0][lrow] = rb0.x; Bs[buf][lk + 1][lrow] = rb0.y;
        Bs[buf][lk + 2][lrow] = rb0.z; Bs[buf][lk + 3][lrow] = rb0.w;
    };

    float acc[8][4] = {};

    ldg_stage(0);
    sts_stage(0);
    __syncthreads();

    for (int s = 0; s < 16; s++) {
        int cur = s & 1;
        if (s < 15) ldg_stage((s + 1) * 16);
#pragma unroll
        for (int kk = 0; kk < 16; kk++) {
            float4 a0 = *(const float4*)&As[cur][kk][ty * 8];
            float4 a1 = *(const float4*)&As[cur][kk][ty * 8 + 4];
            float4 b0 = *(const float4*)&Bs[cur][kk][tx * 4];
            float av[8] = {a0.x, a0.y, a0.z, a0.w, a1.x, a1.y, a1.z, a1.w};
            float bv[4] = {b0.x, b0.y, b0.z, b0.w};
#pragma unroll
            for (int ii = 0; ii < 8; ii++)
#pragma unroll
                for (int jj = 0; jj < 4; jj++)
                    acc[ii][jj] += av[ii] * bv[jj];
        }
        if (s < 15) {
            sts_stage(cur ^ 1);    // ping-pong: single barrier per stage
            __syncthreads();
        }
    }

    // ---- epilogue: finalize scores ----
    int i0 = it * 128 + ty * 8;
    int j0 = jt * 64 + tx * 4;
    float cst = g_cst;
    float4 u0 = *(const float4*)&g_u[b * N_SEQ + i0];
    float4 u1 = *(const float4*)&g_u[b * N_SEQ + i0 + 4];
    float4 v0 = *(const float4*)&g_v[b * N_SEQ + j0];
    float uu[8] = {u0.x, u0.y, u0.z, u0.w, u1.x, u1.y, u1.z, u1.w};
    float vv[4] = {v0.x, v0.y, v0.z, v0.w};

#pragma unroll
    for (int ii = 0; ii < 8; ii++)
#pragma unroll
        for (int jj = 0; jj < 4; jj++)
            acc[ii][jj] = (acc[ii][jj] + uu[ii] + vv[jj] + cst) * 0.0625f;

    // ---- relation-mask multiply + streaming store (Rt: j-contiguous) ----
    const size_t NN = (size_t)N_SEQ * N_SEQ;
#pragma unroll
    for (int ii = 0; ii < 8; ii++) {
        int i = i0 + ii;
        const float* rtp = g_Rt + (size_t)i * N_SEQ + j0;
        float* op = out + (size_t)(b * RREL) * NN + (size_t)i * N_SEQ + j0;
#pragma unroll
        for (int r = 0; r < RREL; r++) {
            float4 m0 = __ldg((const float4*)(rtp + (size_t)r * NN));
            float4 o0;
            o0.x = acc[ii][0] * m0.x;
            o0.y = acc[ii][1] * m0.y;
            o0.z = acc[ii][2] * m0.z;
            o0.w = acc[ii][3] * m0.w;
            __stcs((float4*)(op + (size_t)r * NN), o0);
        }
    }
}

// ---------------------------------------------------------------------------
extern "C" void kernel_launch(void* const* d_in, const int* in_sizes, int n_in,
                              void* d_out, int out_size) {
    const float* Q    = (const float*)d_in[0];
    const float* K    = (const float*)d_in[1];
    const float* Wq   = (const float*)d_in[2];
    const float* bq   = (const float*)d_in[3];
    const float* Wk   = (const float*)d_in[4];
    const float* bk   = (const float*)d_in[5];
    const float* Rmap = (const float*)d_in[6];
    float* out = (float*)d_out;

    prep_w<<<257, 256>>>(Wq, Wk, bq, bk);
    mega<<<256 + 4096 + 1024, 256>>>(Q, K, Rmap);
    main_fused<<<dim3(8, 128), 256>>>(K, out);
}

// round 12
// speedup vs baseline: 1.0398x; 1.0398x over previous
#include <cuda_runtime.h>

#define BATCH 8
#define N_SEQ 1024
#define CDIM  256
#define RREL  16

// Padded smem strides (R9: 2-way STS conflicts instead of 4-way)
#define SA 132
#define SB 68

// Scratch (device globals — no allocation allowed)
__device__ __align__(16) float g_Gt[CDIM * CDIM];        // Gt[m][k] = sum_c Wq[c][k]*Wk[c][m]
__device__ __align__(16) float g_wu[CDIM];               // Wq^T @ b_k
__device__ __align__(16) float g_wv[CDIM];               // Wk^T @ b_q
__device__ float g_cst;                                  // b_q . b_k
__device__ __align__(16) float g_A[BATCH * N_SEQ * CDIM];// Q @ G  (8 MB)
__device__ __align__(16) float g_u[BATCH * N_SEQ];
__device__ __align__(16) float g_v[BATCH * N_SEQ];
__device__ __align__(16) float g_Rt[RREL * N_SEQ * N_SEQ]; // R_map transposed [r][i][j] (64 MB)

// ---------------------------------------------------------------------------
// prep_w: blocks 0..255 compute Gt; block 256 computes wu/wv/cst.
// R12: wu/wv parallelized over c ACROSS WARPS (warp w owns 32 c-values),
// per-lane 16 structurally independent loads per iteration -> latency
// pipelined by construction, then smem cross-warp reduction.
// ---------------------------------------------------------------------------
__global__ void prep_w(const float* __restrict__ Wq, const float* __restrict__ Wk,
                       const float* __restrict__ bq, const float* __restrict__ bk) {
    int tid = threadIdx.x;

    if (blockIdx.x == 256) {
        __shared__ float pu[8][256];
        __shared__ float pv[8][256];
        int warp = tid >> 5;
        int lane = tid & 31;

        float au[8] = {}, av[8] = {};
        for (int cc = 0; cc < 32; cc++) {
            int c = warp * 32 + cc;
            float bkc = bk[c];
            float bqc = bq[c];
#pragma unroll
            for (int g = 0; g < 8; g++) {
                int k = lane + g * 32;
                au[g] += Wq[c * CDIM + k] * bkc;
                av[g] += Wk[c * CDIM + k] * bqc;
            }
        }
#pragma unroll
        for (int g = 0; g < 8; g++) {
            pu[warp][lane + g * 32] = au[g];
            pv[warp][lane + g * 32] = av[g];
        }
        __syncthreads();

        // each thread reduces 8 partials for its k = tid
        float fu = 0.f, fv = 0.f;
#pragma unroll
        for (int w = 0; w < 8; w++) {
            fu += pu[w][tid];
            fv += pv[w][tid];
        }
        g_wu[tid] = fu;
        g_wv[tid] = fv;

        // cst = bq . bk (reuse pu row 0 as scratch)
        __syncthreads();
        pu[0][tid] = bq[tid] * bk[tid];
        __syncthreads();
        for (int s = 128; s > 0; s >>= 1) {
            if (tid < s) pu[0][tid] += pu[0][tid + s];
            __syncthreads();
        }
        if (tid == 0) g_cst = pu[0][0];
        return;
    }

    int bx = blockIdx.x;
    int mt = bx >> 4;
    int kt = bx & 15;
    int tm = tid >> 4;
    int tk = tid & 15;
    int lc = tid >> 4;
    int li = tid & 15;

    __shared__ float sq[16][16];
    __shared__ float sk[16][16];

    float acc = 0.f;
    for (int c0 = 0; c0 < CDIM; c0 += 16) {
        sq[lc][li] = Wq[(c0 + lc) * CDIM + kt * 16 + li];
        sk[lc][li] = Wk[(c0 + lc) * CDIM + mt * 16 + li];
        __syncthreads();
#pragma unroll
        for (int cc = 0; cc < 16; cc++)
            acc += sq[cc][tk] * sk[cc][tm];
        __syncthreads();
    }
    g_Gt[(mt * 16 + tm) * CDIM + kt * 16 + tk] = acc;
}

// ---------------------------------------------------------------------------
// mega: heterogeneous launch that fills the machine.
//   blocks [0,256):         gemm_A  (A = Q @ G), 128x64 tile, 8x4 micro
//   blocks [256,4352):      Rt transpose (R_map[i][j][r] -> g_Rt[r][i][j])
//   blocks [4352,5376):     compute_uv
// ---------------------------------------------------------------------------
__global__ __launch_bounds__(256, 2) void mega(const float* __restrict__ Q,
                                               const float* __restrict__ K,
                                               const float* __restrict__ Rmap) {
    __shared__ __align__(16) float smem[6400];   // union buffer (25.6 KB)
    int tid = threadIdx.x;
    int bx = blockIdx.x;

    if (bx < 256) {
        // ================= gemm_A branch =================
        int mt = bx & 3;
        int rt = bx >> 2;
        int tx = tid & 15;
        int ty = tid >> 4;
        int lrow = tid >> 2;
        int lk = (tid & 3) << 2;

        float (*As)[16][SA] = (float (*)[16][SA])smem;
        float (*Bs)[16][SB] = (float (*)[16][SB])(smem + 2 * 16 * SA);

        const float* Ap = Q + (size_t)rt * 128 * CDIM;
        const float* Bp = g_Gt + (size_t)mt * 64 * CDIM;

        float4 ra0, ra1, rb0;

        auto ldg_stage = [&](int k0) {
            ra0 = *(const float4*)(Ap + (size_t)lrow * CDIM + k0 + lk);
            ra1 = *(const float4*)(Ap + (size_t)(64 + lrow) * CDIM + k0 + lk);
            rb0 = *(const float4*)(Bp + (size_t)lrow * CDIM + k0 + lk);
        };
        auto sts_stage = [&](int buf) {
            As[buf][lk + 0][lrow] = ra0.x; As[buf][lk + 1][lrow] = ra0.y;
            As[buf][lk + 2][lrow] = ra0.z; As[buf][lk + 3][lrow] = ra0.w;
            As[buf][lk + 0][64 + lrow] = ra1.x; As[buf][lk + 1][64 + lrow] = ra1.y;
            As[buf][lk + 2][64 + lrow] = ra1.z; As[buf][lk + 3][64 + lrow] = ra1.w;
            Bs[buf][lk + 0][lrow] = rb0.x; Bs[buf][lk + 1][lrow] = rb0.y;
            Bs[buf][lk + 2][lrow] = rb0.z; Bs[buf][lk + 3][lrow] = rb0.w;
        };

        float acc[8][4] = {};

        ldg_stage(0);
        sts_stage(0);
        __syncthreads();

        for (int s = 0; s < 16; s++) {
            int cur = s & 1;
            if (s < 15) ldg_stage((s + 1) * 16);
#pragma unroll
            for (int kk = 0; kk < 16; kk++) {
                float4 a0 = *(const float4*)&As[cur][kk][ty * 8];
                float4 a1 = *(const float4*)&As[cur][kk][ty * 8 + 4];
                float4 b0 = *(const float4*)&Bs[cur][kk][tx * 4];
                float av[8] = {a0.x, a0.y, a0.z, a0.w, a1.x, a1.y, a1.z, a1.w};
                float bv[4] = {b0.x, b0.y, b0.z, b0.w};
#pragma unroll
                for (int ii = 0; ii < 8; ii++)
#pragma unroll
                    for (int jj = 0; jj < 4; jj++)
                        acc[ii][jj] += av[ii] * bv[jj];
            }
            if (s < 15) {
                sts_stage(cur ^ 1);
                __syncthreads();
            }
        }

        int row = rt * 128 + ty * 8;
        int m = mt * 64 + tx * 4;
#pragma unroll
        for (int ii = 0; ii < 8; ii++) {
            float4 o = {acc[ii][0], acc[ii][1], acc[ii][2], acc[ii][3]};
            *(float4*)&g_A[(size_t)(row + ii) * CDIM + m] = o;
        }
        return;
    }

    if (bx < 256 + 4096) {
        // ================= Rt transpose branch =================
        int tb = bx - 256;                  // 0..4095
        int i  = tb >> 2;                   // 0..1023
        int j0 = (tb & 3) << 8;             // 0,256,512,768
        float* s = smem;                    // uses 256*17 = 4352 floats
        const float4* src = (const float4*)(Rmap + ((size_t)i * N_SEQ + j0) * RREL);
#pragma unroll
        for (int q = 0; q < 4; q++) {
            int idx = q * 256 + tid;        // 0..1023 float4s
            float4 f = src[idx];
            int j = idx >> 2;
            int rq = (idx & 3) << 2;
            s[j * 17 + rq + 0] = f.x; s[j * 17 + rq + 1] = f.y;
            s[j * 17 + rq + 2] = f.z; s[j * 17 + rq + 3] = f.w;
        }
        __syncthreads();
        int jq = (tid & 63) << 2;
        int r0 = tid >> 6;                  // 0..3
#pragma unroll
        for (int w = 0; w < 4; w++) {
            int r = r0 * 4 + w;
            float4 o;
            o.x = s[(jq + 0) * 17 + r];
            o.y = s[(jq + 1) * 17 + r];
            o.z = s[(jq + 2) * 17 + r];
            o.w = s[(jq + 3) * 17 + r];
            *(float4*)&g_Rt[((size_t)r * N_SEQ + i) * N_SEQ + j0 + jq] = o;
        }
        return;
    }

    // ================= compute_uv branch =================
    {
        int ub = bx - (256 + 4096);         // 0..1023
        int warp = tid >> 5;
        int lane = tid & 31;
        int row = ub * 8 + warp;
        const float* qr = Q + (size_t)row * CDIM;
        const float* kr = K + (size_t)row * CDIM;
        float au = 0.f, av = 0.f;
#pragma unroll
        for (int t = 0; t < 8; t++) {
            int c = lane + t * 32;
            au += qr[c] * g_wu[c];
            av += kr[c] * g_wv[c];
        }
#pragma unroll
        for (int o = 16; o > 0; o >>= 1) {
            au += __shfl_down_sync(0xffffffffu, au, o);
            av += __shfl_down_sync(0xffffffffu, av, o);
        }
        if (lane == 0) {
            g_u[row] = au;
            g_v[row] = av;
        }
    }
}

// ---------------------------------------------------------------------------
// main_fused (identical to R9/R10 best): 128(i) x 64(j) tile, 8x4 micro,
// 256 threads, occ-3, padded smem, Rt epilogue, streaming stores.
// ---------------------------------------------------------------------------
__global__ __launch_bounds__(256, 3) void main_fused(const float* __restrict__ Key,
                                                     float* __restrict__ out) {
    int b = blockIdx.x;
    int tile = blockIdx.y;        // 0..127
    int it = tile >> 4;           // 0..7   (128 i-rows each)
    int jt = tile & 15;           // 0..15  (64 j-cols each)
    int tid = threadIdx.x;
    int tx = tid & 15;            // j dir (4 each)
    int ty = tid >> 4;            // i dir (8 each)
    int lrow = tid >> 2;          // 0..63
    int lk = (tid & 3) << 2;      // 0,4,8,12

    __shared__ __align__(16) float As[2][16][SA];  // [buf][k][i] padded
    __shared__ __align__(16) float Bs[2][16][SB];  // [buf][k][j] padded

    const float* Ap = g_A + ((size_t)b * N_SEQ + it * 128) * CDIM;
    const float* Bp = Key + ((size_t)b * N_SEQ + jt * 64) * CDIM;

    float4 ra0, ra1, rb0;

    auto ldg_stage = [&](int k0) {
        ra0 = *(const float4*)(Ap + (size_t)lrow * CDIM + k0 + lk);
        ra1 = *(const float4*)(Ap + (size_t)(64 + lrow) * CDIM + k0 + lk);
        rb0 = *(const float4*)(Bp + (size_t)lrow * CDIM + k0 + lk);
    };
    auto sts_stage = [&](int buf) {
        As[buf][lk + 0][lrow] = ra0.x; As[buf][lk + 1][lrow] = ra0.y;
        As[buf][lk + 2][lrow] = ra0.z; As[buf][lk + 3][lrow] = ra0.w;
        As[buf][lk + 0][64 + lrow] = ra1.x; As[buf][lk + 1][64 + lrow] = ra1.y;
        As[buf][lk + 2][64 + lrow] = ra1.z; As[buf][lk + 3][64 + lrow] = ra1.w;
        Bs[buf][lk + 0][lrow] = rb0.x; Bs[buf][lk + 1][lrow] = rb0.y;
        Bs[buf][lk + 2][lrow] = rb0.z; Bs[buf][lk + 3][lrow] = rb0.w;
    };

    float acc[8][4] = {};

    ldg_stage(0);
    sts_stage(0);
    __syncthreads();

    for (int s = 0; s < 16; s++) {
        int cur = s & 1;
        if (s < 15) ldg_stage((s + 1) * 16);
#pragma unroll
        for (int kk = 0; kk < 16; kk++) {
            float4 a0 = *(const float4*)&As[cur][kk][ty * 8];
            float4 a1 = *(const float4*)&As[cur][kk][ty * 8 + 4];
            float4 b0 = *(const float4*)&Bs[cur][kk][tx * 4];
            float av[8] = {a0.x, a0.y, a0.z, a0.w, a1.x, a1.y, a1.z, a1.w};
            float bv[4] = {b0.x, b0.y, b0.z, b0.w};
#pragma unroll
            for (int ii = 0; ii < 8; ii++)
#pragma unroll
                for (int jj = 0; jj < 4; jj++)
                    acc[ii][jj] += av[ii] * bv[jj];
        }
        if (s < 15) {
            sts_stage(cur ^ 1);    // ping-pong: single barrier per stage
            __syncthreads();
        }
    }

    // ---- epilogue: finalize scores ----
    int i0 = it * 128 + ty * 8;
    int j0 = jt * 64 + tx * 4;
    float cst = g_cst;
    float4 u0 = *(const float4*)&g_u[b * N_SEQ + i0];
    float4 u1 = *(const float4*)&g_u[b * N_SEQ + i0 + 4];
    float4 v0 = *(const float4*)&g_v[b * N_SEQ + j0];
    float uu[8] = {u0.x, u0.y, u0.z, u0.w, u1.x, u1.y, u1.z, u1.w};
    float vv[4] = {v0.x, v0.y, v0.z, v0.w};

#pragma unroll
    for (int ii = 0; ii < 8; ii++)
#pragma unroll
        for (int jj = 0; jj < 4; jj++)
            acc[ii][jj] = (acc[ii][jj] + uu[ii] + vv[jj] + cst) * 0.0625f;

    // ---- relation-mask multiply + streaming store (Rt: j-contiguous) ----
    const size_t NN = (size_t)N_SEQ * N_SEQ;
#pragma unroll
    for (int ii = 0; ii < 8; ii++) {
        int i = i0 + ii;
        const float* rtp = g_Rt + (size_t)i * N_SEQ + j0;
        float* op = out + (size_t)(b * RREL) * NN + (size_t)i * N_SEQ + j0;
#pragma unroll
        for (int r = 0; r < RREL; r++) {
            float4 m0 = __ldg((const float4*)(rtp + (size_t)r * NN));
            float4 o0;
            o0.x = acc[ii][0] * m0.x;
            o0.y = acc[ii][1] * m0.y;
            o0.z = acc[ii][2] * m0.z;
            o0.w = acc[ii][3] * m0.w;
            __stcs((float4*)(op + (size_t)r * NN), o0);
        }
    }
}

// ---------------------------------------------------------------------------
extern "C" void kernel_launch(void* const* d_in, const int* in_sizes, int n_in,
                              void* d_out, int out_size) {
    const float* Q    = (const float*)d_in[0];
    const float* K    = (const float*)d_in[1];
    const float* Wq   = (const float*)d_in[2];
    const float* bq   = (const float*)d_in[3];
    const float* Wk   = (const float*)d_in[4];
    const float* bk   = (const float*)d_in[5];
    const float* Rmap = (const float*)d_in[6];
    float* out = (float*)d_out;

    prep_w<<<257, 256>>>(Wq, Wk, bq, bk);
    mega<<<256 + 4096 + 1024, 256>>>(Q, K, Rmap);
    main_fused<<<dim3(8, 128), 256>>>(K, out);
}

// round 13
// speedup vs baseline: 1.0622x; 1.0215x over previous
#include <cuda_runtime.h>

#define BATCH 8
#define N_SEQ 1024
#define CDIM  256
#define RREL  16

// Padded smem strides (R9: 2-way STS conflicts instead of 4-way)
#define SA 132
#define SB 68

// Scratch (device globals — no allocation allowed)
__device__ __align__(16) float g_Gt[CDIM * CDIM];        // Gt[m][k] = sum_c Wq[c][k]*Wk[c][m]
__device__ __align__(16) float g_wu[CDIM];               // Wq^T @ b_k
__device__ __align__(16) float g_wv[CDIM];               // Wk^T @ b_q
__device__ float g_cst;                                  // b_q . b_k
__device__ __align__(16) float g_A[BATCH * N_SEQ * CDIM];// Q @ G  (8 MB)
__device__ __align__(16) float g_u[BATCH * N_SEQ];
__device__ __align__(16) float g_v[BATCH * N_SEQ];
__device__ __align__(16) float g_Rt[RREL * N_SEQ * N_SEQ]; // R_map transposed [r][i][j] (64 MB)

// ---------------------------------------------------------------------------
// prep_w: blocks 0..255 compute Gt; block 256 computes wu/wv/cst.
// R13: Gt branch restructured to ONE load phase (full 16-col slices of Wq/Wk
// staged to smem, MLP~8) + ONE barrier + 256-deep smem dot product, instead
// of 16 barrier-serialized cold-DRAM rounds (the actual 30us straggler).
// ---------------------------------------------------------------------------
__global__ void prep_w(const float* __restrict__ Wq, const float* __restrict__ Wk,
                       const float* __restrict__ bq, const float* __restrict__ bk) {
    __shared__ __align__(16) float sm[8192];   // 32 KB union
    int tid = threadIdx.x;

    if (blockIdx.x == 256) {
        // ---- wu/wv/cst (R12 structure, uses 16 KB of sm) ----
        float (*pu)[256] = (float (*)[256])sm;
        float (*pv)[256] = (float (*)[256])(sm + 2048);
        int warp = tid >> 5;
        int lane = tid & 31;

        float au[8] = {}, av[8] = {};
        for (int cc = 0; cc < 32; cc++) {
            int c = warp * 32 + cc;
            float bkc = bk[c];
            float bqc = bq[c];
#pragma unroll
            for (int g = 0; g < 8; g++) {
                int k = lane + g * 32;
                au[g] += Wq[c * CDIM + k] * bkc;
                av[g] += Wk[c * CDIM + k] * bqc;
            }
        }
#pragma unroll
        for (int g = 0; g < 8; g++) {
            pu[warp][lane + g * 32] = au[g];
            pv[warp][lane + g * 32] = av[g];
        }
        __syncthreads();

        float fu = 0.f, fv = 0.f;
#pragma unroll
        for (int w = 0; w < 8; w++) {
            fu += pu[w][tid];
            fv += pv[w][tid];
        }
        g_wu[tid] = fu;
        g_wv[tid] = fv;

        __syncthreads();
        pu[0][tid] = bq[tid] * bk[tid];
        __syncthreads();
        for (int s = 128; s > 0; s >>= 1) {
            if (tid < s) pu[0][tid] += pu[0][tid + s];
            __syncthreads();
        }
        if (tid == 0) g_cst = pu[0][0];
        return;
    }

    // ---- Gt tile: single load phase, single barrier ----
    int bx = blockIdx.x;
    int mt = bx >> 4;
    int kt = bx & 15;
    float* sq = sm;            // [256][16]  Wq[:, kt*16 .. +16)
    float* sk = sm + 4096;     // [256][16]  Wk[:, mt*16 .. +16)

    // 1024 float4 loads per matrix; 4 per thread; all independent (MLP 8)
#pragma unroll
    for (int q = 0; q < 4; q++) {
        int idx = q * 256 + tid;        // 0..1023
        int row = idx >> 2;
        int c4 = (idx & 3) << 2;
        float4 fq = *(const float4*)(Wq + (size_t)row * CDIM + kt * 16 + c4);
        float4 fk = *(const float4*)(Wk + (size_t)row * CDIM + mt * 16 + c4);
        *(float4*)&sq[row * 16 + c4] = fq;
        *(float4*)&sk[row * 16 + c4] = fk;
    }
    __syncthreads();

    int tm = tid >> 4;
    int tk = tid & 15;
    float a0 = 0.f, a1 = 0.f, a2 = 0.f, a3 = 0.f;
#pragma unroll 4
    for (int c = 0; c < CDIM; c += 4) {
        a0 += sk[(c + 0) * 16 + tm] * sq[(c + 0) * 16 + tk];
        a1 += sk[(c + 1) * 16 + tm] * sq[(c + 1) * 16 + tk];
        a2 += sk[(c + 2) * 16 + tm] * sq[(c + 2) * 16 + tk];
        a3 += sk[(c + 3) * 16 + tm] * sq[(c + 3) * 16 + tk];
    }
    g_Gt[(mt * 16 + tm) * CDIM + kt * 16 + tk] = (a0 + a1) + (a2 + a3);
}

// ---------------------------------------------------------------------------
// mega: heterogeneous launch that fills the machine.
//   blocks [0,256):         gemm_A  (A = Q @ G), 128x64 tile, 8x4 micro
//   blocks [256,4352):      Rt transpose (R_map[i][j][r] -> g_Rt[r][i][j])
//   blocks [4352,5376):     compute_uv
// ---------------------------------------------------------------------------
__global__ __launch_bounds__(256, 2) void mega(const float* __restrict__ Q,
                                               const float* __restrict__ K,
                                               const float* __restrict__ Rmap) {
    __shared__ __align__(16) float smem[6400];   // union buffer (25.6 KB)
    int tid = threadIdx.x;
    int bx = blockIdx.x;

    if (bx < 256) {
        // ================= gemm_A branch =================
        int mt = bx & 3;
        int rt = bx >> 2;
        int tx = tid & 15;
        int ty = tid >> 4;
        int lrow = tid >> 2;
        int lk = (tid & 3) << 2;

        float (*As)[16][SA] = (float (*)[16][SA])smem;
        float (*Bs)[16][SB] = (float (*)[16][SB])(smem + 2 * 16 * SA);

        const float* Ap = Q + (size_t)rt * 128 * CDIM;
        const float* Bp = g_Gt + (size_t)mt * 64 * CDIM;

        float4 ra0, ra1, rb0;

        auto ldg_stage = [&](int k0) {
            ra0 = *(const float4*)(Ap + (size_t)lrow * CDIM + k0 + lk);
            ra1 = *(const float4*)(Ap + (size_t)(64 + lrow) * CDIM + k0 + lk);
            rb0 = *(const float4*)(Bp + (size_t)lrow * CDIM + k0 + lk);
        };
        auto sts_stage = [&](int buf) {
            As[buf][lk + 0][lrow] = ra0.x; As[buf][lk + 1][lrow] = ra0.y;
            As[buf][lk + 2][lrow] = ra0.z; As[buf][lk + 3][lrow] = ra0.w;
            As[buf][lk + 0][64 + lrow] = ra1.x; As[buf][lk + 1][64 + lrow] = ra1.y;
            As[buf][lk + 2][64 + lrow] = ra1.z; As[buf][lk + 3][64 + lrow] = ra1.w;
            Bs[buf][lk + 0][lrow] = rb0.x; Bs[buf][lk + 1][lrow] = rb0.y;
            Bs[buf][lk + 2][lrow] = rb0.z; Bs[buf][lk + 3][lrow] = rb0.w;
        };

        float acc[8][4] = {};

        ldg_stage(0);
        sts_stage(0);
        __syncthreads();

        for (int s = 0; s < 16; s++) {
            int cur = s & 1;
            if (s < 15) ldg_stage((s + 1) * 16);
#pragma unroll
            for (int kk = 0; kk < 16; kk++) {
                float4 a0 = *(const float4*)&As[cur][kk][ty * 8];
                float4 a1 = *(const float4*)&As[cur][kk][ty * 8 + 4];
                float4 b0 = *(const float4*)&Bs[cur][kk][tx * 4];
                float av[8] = {a0.x, a0.y, a0.z, a0.w, a1.x, a1.y, a1.z, a1.w};
                float bv[4] = {b0.x, b0.y, b0.z, b0.w};
#pragma unroll
                for (int ii = 0; ii < 8; ii++)
#pragma unroll
                    for (int jj = 0; jj < 4; jj++)
                        acc[ii][jj] += av[ii] * bv[jj];
            }
            if (s < 15) {
                sts_stage(cur ^ 1);
                __syncthreads();
            }
        }

        int row = rt * 128 + ty * 8;
        int m = mt * 64 + tx * 4;
#pragma unroll
        for (int ii = 0; ii < 8; ii++) {
            float4 o = {acc[ii][0], acc[ii][1], acc[ii][2], acc[ii][3]};
            *(float4*)&g_A[(size_t)(row + ii) * CDIM + m] = o;
        }
        return;
    }

    if (bx < 256 + 4096) {
        // ================= Rt transpose branch =================
        int tb = bx - 256;                  // 0..4095
        int i  = tb >> 2;                   // 0..1023
        int j0 = (tb & 3) << 8;             // 0,256,512,768
        float* s = smem;                    // uses 256*17 = 4352 floats
        const float4* src = (const float4*)(Rmap + ((size_t)i * N_SEQ + j0) * RREL);
#pragma unroll
        for (int q = 0; q < 4; q++) {
            int idx = q * 256 + tid;        // 0..1023 float4s
            float4 f = src[idx];
            int j = idx >> 2;
            int rq = (idx & 3) << 2;
            s[j * 17 + rq + 0] = f.x; s[j * 17 + rq + 1] = f.y;
            s[j * 17 + rq + 2] = f.z; s[j * 17 + rq + 3] = f.w;
        }
        __syncthreads();
        int jq = (tid & 63) << 2;
        int r0 = tid >> 6;                  // 0..3
#pragma unroll
        for (int w = 0; w < 4; w++) {
            int r = r0 * 4 + w;
            float4 o;
            o.x = s[(jq + 0) * 17 + r];
            o.y = s[(jq + 1) * 17 + r];
            o.z = s[(jq + 2) * 17 + r];
            o.w = s[(jq + 3) * 17 + r];
            *(float4*)&g_Rt[((size_t)r * N_SEQ + i) * N_SEQ + j0 + jq] = o;
        }
        return;
    }

    // ================= compute_uv branch =================
    {
        int ub = bx - (256 + 4096);         // 0..1023
        int warp = tid >> 5;
        int lane = tid & 31;
        int row = ub * 8 + warp;
        const float* qr = Q + (size_t)row * CDIM;
        const float* kr = K + (size_t)row * CDIM;
        float au = 0.f, av = 0.f;
#pragma unroll
        for (int t = 0; t < 8; t++) {
            int c = lane + t * 32;
            au += qr[c] * g_wu[c];
            av += kr[c] * g_wv[c];
        }
#pragma unroll
        for (int o = 16; o > 0; o >>= 1) {
            au += __shfl_down_sync(0xffffffffu, au, o);
            av += __shfl_down_sync(0xffffffffu, av, o);
        }
        if (lane == 0) {
            g_u[row] = au;
            g_v[row] = av;
        }
    }
}

// ---------------------------------------------------------------------------
// main_fused (identical to R9/R10 best): 128(i) x 64(j) tile, 8x4 micro,
// 256 threads, occ-3, padded smem, Rt epilogue, streaming stores.
// ---------------------------------------------------------------------------
__global__ __launch_bounds__(256, 3) void main_fused(const float* __restrict__ Key,
                                                     float* __restrict__ out) {
    int b = blockIdx.x;
    int tile = blockIdx.y;        // 0..127
    int it = tile >> 4;           // 0..7   (128 i-rows each)
    int jt = tile & 15;           // 0..15  (64 j-cols each)
    int tid = threadIdx.x;
    int tx = tid & 15;            // j dir (4 each)
    int ty = tid >> 4;            // i dir (8 each)
    int lrow = tid >> 2;          // 0..63
    int lk = (tid & 3) << 2;      // 0,4,8,12

    __shared__ __align__(16) float As[2][16][SA];  // [buf][k][i] padded
    __shared__ __align__(16) float Bs[2][16][SB];  // [buf][k][j] padded

    const float* Ap = g_A + ((size_t)b * N_SEQ + it * 128) * CDIM;
    const float* Bp = Key + ((size_t)b * N_SEQ + jt * 64) * CDIM;

    float4 ra0, ra1, rb0;

    auto ldg_stage = [&](int k0) {
        ra0 = *(const float4*)(Ap + (size_t)lrow * CDIM + k0 + lk);
        ra1 = *(const float4*)(Ap + (size_t)(64 + lrow) * CDIM + k0 + lk);
        rb0 = *(const float4*)(Bp + (size_t)lrow * CDIM + k0 + lk);
    };
    auto sts_stage = [&](int buf) {
        As[buf][lk + 0][lrow] = ra0.x; As[buf][lk + 1][lrow] = ra0.y;
        As[buf][lk + 2][lrow] = ra0.z; As[buf][lk + 3][lrow] = ra0.w;
        As[buf][lk + 0][64 + lrow] = ra1.x; As[buf][lk + 1][64 + lrow] = ra1.y;
        As[buf][lk + 2][64 + lrow] = ra1.z; As[buf][lk + 3][64 + lrow] = ra1.w;
        Bs[buf][lk + 0][lrow] = rb0.x; Bs[buf][lk + 1][lrow] = rb0.y;
        Bs[buf][lk + 2][lrow] = rb0.z; Bs[buf][lk + 3][lrow] = rb0.w;
    };

    float acc[8][4] = {};

    ldg_stage(0);
    sts_stage(0);
    __syncthreads();

    for (int s = 0; s < 16; s++) {
        int cur = s & 1;
        if (s < 15) ldg_stage((s + 1) * 16);
#pragma unroll
        for (int kk = 0; kk < 16; kk++) {
            float4 a0 = *(const float4*)&As[cur][kk][ty * 8];
            float4 a1 = *(const float4*)&As[cur][kk][ty * 8 + 4];
            float4 b0 = *(const float4*)&Bs[cur][kk][tx * 4];
            float av[8] = {a0.x, a0.y, a0.z, a0.w, a1.x, a1.y, a1.z, a1.w};
            float bv[4] = {b0.x, b0.y, b0.z, b0.w};
#pragma unroll
            for (int ii = 0; ii < 8; ii++)
#pragma unroll
                for (int jj = 0; jj < 4; jj++)
                    acc[ii][jj] += av[ii] * bv[jj];
        }
        if (s < 15) {
            sts_stage(cur ^ 1);    // ping-pong: single barrier per stage
            __syncthreads();
        }
    }

    // ---- epilogue: finalize scores ----
    int i0 = it * 128 + ty * 8;
    int j0 = jt * 64 + tx * 4;
    float cst = g_cst;
    float4 u0 = *(const float4*)&g_u[b * N_SEQ + i0];
    float4 u1 = *(const float4*)&g_u[b * N_SEQ + i0 + 4];
    float4 v0 = *(const float4*)&g_v[b * N_SEQ + j0];
    float uu[8] = {u0.x, u0.y, u0.z, u0.w, u1.x, u1.y, u1.z, u1.w};
    float vv[4] = {v0.x, v0.y, v0.z, v0.w};

#pragma unroll
    for (int ii = 0; ii < 8; ii++)
#pragma unroll
        for (int jj = 0; jj < 4; jj++)
            acc[ii][jj] = (acc[ii][jj] + uu[ii] + vv[jj] + cst) * 0.0625f;

    // ---- relation-mask multiply + streaming store (Rt: j-contiguous) ----
    const size_t NN = (size_t)N_SEQ * N_SEQ;
#pragma unroll
    for (int ii = 0; ii < 8; ii++) {
        int i = i0 + ii;
        const float* rtp = g_Rt + (size_t)i * N_SEQ + j0;
        float* op = out + (size_t)(b * RREL) * NN + (size_t)i * N_SEQ + j0;
#pragma unroll
        for (int r = 0; r < RREL; r++) {
            float4 m0 = __ldg((const float4*)(rtp + (size_t)r * NN));
            float4 o0;
            o0.x = acc[ii][0] * m0.x;
            o0.y = acc[ii][1] * m0.y;
            o0.z = acc[ii][2] * m0.z;
            o0.w = acc[ii][3] * m0.w;
            __stcs((float4*)(op + (size_t)r * NN), o0);
        }
    }
}

// ---------------------------------------------------------------------------
extern "C" void kernel_launch(void* const* d_in, const int* in_sizes, int n_in,
                              void* d_out, int out_size) {
    const float* Q    = (const float*)d_in[0];
    const float* K    = (const float*)d_in[1];
    const float* Wq   = (const float*)d_in[2];
    const float* bq   = (const float*)d_in[3];
    const float* Wk   = (const float*)d_in[4];
    const float* bk   = (const float*)d_in[5];
    const float* Rmap = (const float*)d_in[6];
    float* out = (float*)d_out;

    prep_w<<<257, 256>>>(Wq, Wk, bq, bk);
    mega<<<256 + 4096 + 1024, 256>>>(Q, K, Rmap);
    main_fused<<<dim3(8, 128), 256>>>(K, out);
}

// round 14
// speedup vs baseline: 1.1125x; 1.0474x over previous
#include <cuda_runtime.h>

#define BATCH 8
#define N_SEQ 1024
#define CDIM  256
#define RREL  16

// Padded smem strides (R9: 2-way STS conflicts instead of 4-way)
#define SA 132
#define SB 68

// Scratch (device globals — no allocation allowed)
__device__ __align__(16) float g_A[BATCH * N_SEQ * CDIM];  // Q@Wq^T + bq  (8 MB)
__device__ __align__(16) float g_B[BATCH * N_SEQ * CDIM];  // K@Wk^T + bk  (8 MB)
__device__ __align__(16) float g_Rt[RREL * N_SEQ * N_SEQ]; // R_map transposed [r][i][j] (64 MB)

// ---------------------------------------------------------------------------
// mega: the whole pre-pass in ONE launch (R14: prep_w/compute_uv deleted —
// biases are folded into the projections, so scores = g_A . g_B^T exactly).
//   blocks [0,512):       projection GEMMs:
//                           p=0: g_A = Q @ Wq^T + bq   (128x64 tile, 8x4 micro)
//                           p=1: g_B = K @ Wk^T + bk
//   blocks [512,4608):    Rt transpose (R_map[i][j][r] -> g_Rt[r][i][j])
// ---------------------------------------------------------------------------
__global__ __launch_bounds__(256, 2) void mega(const float* __restrict__ Q,
                                               const float* __restrict__ K,
                                               const float* __restrict__ Wq,
                                               const float* __restrict__ bq,
                                               const float* __restrict__ Wk,
                                               const float* __restrict__ bk,
                                               const float* __restrict__ Rmap) {
    __shared__ __align__(16) float smem[6400];   // union buffer (25.6 KB)
    int tid = threadIdx.x;
    int bx = blockIdx.x;

    if (bx < 512) {
        // ================= projection GEMM branch =================
        int p  = bx >> 8;                  // 0: Q-proj, 1: K-proj
        int bb = bx & 255;
        int mt = bb & 3;                   // 64-wide c-tile
        int rt = bb >> 2;                  // 128-row tile
        int tx = tid & 15;
        int ty = tid >> 4;
        int lrow = tid >> 2;
        int lk = (tid & 3) << 2;

        const float* src  = p ? K  : Q;
        const float* W    = p ? Wk : Wq;
        const float* bias = p ? bk : bq;
        float* dst        = p ? g_B : g_A;

        float (*As)[16][SA] = (float (*)[16][SA])smem;
        float (*Bs)[16][SB] = (float (*)[16][SB])(smem + 2 * 16 * SA);

        const float* Ap = src + (size_t)rt * 128 * CDIM;
        const float* Bp = W + (size_t)mt * 64 * CDIM;   // W rows = output channel c

        float4 ra0, ra1, rb0;

        auto ldg_stage = [&](int k0) {
            ra0 = *(const float4*)(Ap + (size_t)lrow * CDIM + k0 + lk);
            ra1 = *(const float4*)(Ap + (size_t)(64 + lrow) * CDIM + k0 + lk);
            rb0 = *(const float4*)(Bp + (size_t)lrow * CDIM + k0 + lk);
        };
        auto sts_stage = [&](int buf) {
            As[buf][lk + 0][lrow] = ra0.x; As[buf][lk + 1][lrow] = ra0.y;
            As[buf][lk + 2][lrow] = ra0.z; As[buf][lk + 3][lrow] = ra0.w;
            As[buf][lk + 0][64 + lrow] = ra1.x; As[buf][lk + 1][64 + lrow] = ra1.y;
            As[buf][lk + 2][64 + lrow] = ra1.z; As[buf][lk + 3][64 + lrow] = ra1.w;
            Bs[buf][lk + 0][lrow] = rb0.x; Bs[buf][lk + 1][lrow] = rb0.y;
            Bs[buf][lk + 2][lrow] = rb0.z; Bs[buf][lk + 3][lrow] = rb0.w;
        };

        float acc[8][4] = {};

        ldg_stage(0);
        sts_stage(0);
        __syncthreads();

        for (int s = 0; s < 16; s++) {
            int cur = s & 1;
            if (s < 15) ldg_stage((s + 1) * 16);
#pragma unroll
            for (int kk = 0; kk < 16; kk++) {
                float4 a0 = *(const float4*)&As[cur][kk][ty * 8];
                float4 a1 = *(const float4*)&As[cur][kk][ty * 8 + 4];
                float4 b0 = *(const float4*)&Bs[cur][kk][tx * 4];
                float av[8] = {a0.x, a0.y, a0.z, a0.w, a1.x, a1.y, a1.z, a1.w};
                float bv[4] = {b0.x, b0.y, b0.z, b0.w};
#pragma unroll
                for (int ii = 0; ii < 8; ii++)
#pragma unroll
                    for (int jj = 0; jj < 4; jj++)
                        acc[ii][jj] += av[ii] * bv[jj];
            }
            if (s < 15) {
                sts_stage(cur ^ 1);
                __syncthreads();
            }
        }

        int row = rt * 128 + ty * 8;
        int m = mt * 64 + tx * 4;
        float4 bv4 = *(const float4*)(bias + m);   // fold bias at store
#pragma unroll
        for (int ii = 0; ii < 8; ii++) {
            float4 o = {acc[ii][0] + bv4.x, acc[ii][1] + bv4.y,
                        acc[ii][2] + bv4.z, acc[ii][3] + bv4.w};
            *(float4*)&dst[(size_t)(row + ii) * CDIM + m] = o;
        }
        return;
    }

    // ================= Rt transpose branch =================
    {
        int tb = bx - 512;                  // 0..4095
        int i  = tb >> 2;                   // 0..1023
        int j0 = (tb & 3) << 8;             // 0,256,512,768
        float* s = smem;                    // uses 256*17 = 4352 floats
        const float4* src = (const float4*)(Rmap + ((size_t)i * N_SEQ + j0) * RREL);
#pragma unroll
        for (int q = 0; q < 4; q++) {
            int idx = q * 256 + tid;        // 0..1023 float4s
            float4 f = src[idx];
            int j = idx >> 2;
            int rq = (idx & 3) << 2;
            s[j * 17 + rq + 0] = f.x; s[j * 17 + rq + 1] = f.y;
            s[j * 17 + rq + 2] = f.z; s[j * 17 + rq + 3] = f.w;
        }
        __syncthreads();
        int jq = (tid & 63) << 2;
        int r0 = tid >> 6;                  // 0..3
#pragma unroll
        for (int w = 0; w < 4; w++) {
            int r = r0 * 4 + w;
            float4 o;
            o.x = s[(jq + 0) * 17 + r];
            o.y = s[(jq + 1) * 17 + r];
            o.z = s[(jq + 2) * 17 + r];
            o.w = s[(jq + 3) * 17 + r];
            *(float4*)&g_Rt[((size_t)r * N_SEQ + i) * N_SEQ + j0 + jq] = o;
        }
    }
}

// ---------------------------------------------------------------------------
// main_fused: 128(i) x 64(j) tile, 8x4 micro, 256 threads, occ-3,
// padded smem, Rt epilogue, streaming stores. R14: B operand is g_B
// (bias-folded K projection); no u/v/cst terms.
//   scores = (g_A[b,i,:] . g_B[b,j,:]) / 16
//   out[b,r,i,j] = scores * Rt[r,i,j]
// ---------------------------------------------------------------------------
__global__ __launch_bounds__(256, 3) void main_fused(float* __restrict__ out) {
    int b = blockIdx.x;
    int tile = blockIdx.y;        // 0..127
    int it = tile >> 4;           // 0..7   (128 i-rows each)
    int jt = tile & 15;           // 0..15  (64 j-cols each)
    int tid = threadIdx.x;
    int tx = tid & 15;            // j dir (4 each)
    int ty = tid >> 4;            // i dir (8 each)
    int lrow = tid >> 2;          // 0..63
    int lk = (tid & 3) << 2;      // 0,4,8,12

    __shared__ __align__(16) float As[2][16][SA];  // [buf][k][i] padded
    __shared__ __align__(16) float Bs[2][16][SB];  // [buf][k][j] padded

    const float* Ap = g_A + ((size_t)b * N_SEQ + it * 128) * CDIM;
    const float* Bp = g_B + ((size_t)b * N_SEQ + jt * 64) * CDIM;

    float4 ra0, ra1, rb0;

    auto ldg_stage = [&](int k0) {
        ra0 = *(const float4*)(Ap + (size_t)lrow * CDIM + k0 + lk);
        ra1 = *(const float4*)(Ap + (size_t)(64 + lrow) * CDIM + k0 + lk);
        rb0 = *(const float4*)(Bp + (size_t)lrow * CDIM + k0 + lk);
    };
    auto sts_stage = [&](int buf) {
        As[buf][lk + 0][lrow] = ra0.x; As[buf][lk + 1][lrow] = ra0.y;
        As[buf][lk + 2][lrow] = ra0.z; As[buf][lk + 3][lrow] = ra0.w;
        As[buf][lk + 0][64 + lrow] = ra1.x; As[buf][lk + 1][64 + lrow] = ra1.y;
        As[buf][lk + 2][64 + lrow] = ra1.z; As[buf][lk + 3][64 + lrow] = ra1.w;
        Bs[buf][lk + 0][lrow] = rb0.x; Bs[buf][lk + 1][lrow] = rb0.y;
        Bs[buf][lk + 2][lrow] = rb0.z; Bs[buf][lk + 3][lrow] = rb0.w;
    };

    float acc[8][4] = {};

    ldg_stage(0);
    sts_stage(0);
    __syncthreads();

    for (int s = 0; s < 16; s++) {
        int cur = s & 1;
        if (s < 15) ldg_stage((s + 1) * 16);
#pragma unroll
        for (int kk = 0; kk < 16; kk++) {
            float4 a0 = *(const float4*)&As[cur][kk][ty * 8];
            float4 a1 = *(const float4*)&As[cur][kk][ty * 8 + 4];
            float4 b0 = *(const float4*)&Bs[cur][kk][tx * 4];
            float av[8] = {a0.x, a0.y, a0.z, a0.w, a1.x, a1.y, a1.z, a1.w};
            float bv[4] = {b0.x, b0.y, b0.z, b0.w};
#pragma unroll
            for (int ii = 0; ii < 8; ii++)
#pragma unroll
                for (int jj = 0; jj < 4; jj++)
                    acc[ii][jj] += av[ii] * bv[jj];
        }
        if (s < 15) {
            sts_stage(cur ^ 1);    // ping-pong: single barrier per stage
            __syncthreads();
        }
    }

    // ---- epilogue: scale only (biases already folded into g_A/g_B) ----
    int i0 = it * 128 + ty * 8;
    int j0 = jt * 64 + tx * 4;
#pragma unroll
    for (int ii = 0; ii < 8; ii++)
#pragma unroll
        for (int jj = 0; jj < 4; jj++)
            acc[ii][jj] *= 0.0625f;

    // ---- relation-mask multiply + streaming store (Rt: j-contiguous) ----
    const size_t NN = (size_t)N_SEQ * N_SEQ;
#pragma unroll
    for (int ii = 0; ii < 8; ii++) {
        int i = i0 + ii;
        const float* rtp = g_Rt + (size_t)i * N_SEQ + j0;
        float* op = out + (size_t)(b * RREL) * NN + (size_t)i * N_SEQ + j0;
#pragma unroll
        for (int r = 0; r < RREL; r++) {
            float4 m0 = __ldg((const float4*)(rtp + (size_t)r * NN));
            float4 o0;
            o0.x = acc[ii][0] * m0.x;
            o0.y = acc[ii][1] * m0.y;
            o0.z = acc[ii][2] * m0.z;
            o0.w = acc[ii][3] * m0.w;
            __stcs((float4*)(op + (size_t)r * NN), o0);
        }
    }
}

// ---------------------------------------------------------------------------
extern "C" void kernel_launch(void* const* d_in, const int* in_sizes, int n_in,
                              void* d_out, int out_size) {
    const float* Q    = (const float*)d_in[0];
    const float* K    = (const float*)d_in[1];
    const float* Wq   = (const float*)d_in[2];
    const float* bq   = (const float*)d_in[3];
    const float* Wk   = (const float*)d_in[4];
    const float* bk   = (const float*)d_in[5];
    const float* Rmap = (const float*)d_in[6];
    float* out = (float*)d_out;

    mega<<<512 + 4096, 256>>>(Q, K, Wq, bq, Wk, bk, Rmap);
    main_fused<<<dim3(8, 128), 256>>>(out);
}